// round 4
// baseline (speedup 1.0000x reference)
#include <cuda_runtime.h>
#include <cstdint>

// out[b,t,a] = start_state[b,a] + (t/255) * patterns[iid[b], t, a]
// B=256, T=256, AD=64. Per CTA: one (b, 64-t chunk) = 16KB contiguous slab of
// patterns, fetched with ONE cp.async.bulk (TMA-class bulk engine) so bytes in
// flight are decoupled from warp scoreboards. Compute from smem, STG out.

#define B_   256
#define T_   256
#define AD_  64
#define TPB  256
#define CHUNK_T 64
#define CHUNK_BYTES (CHUNK_T * AD_ * 4)   // 16384

__global__ __launch_bounds__(TPB)
void traj_kernel(const float* __restrict__ start_state,    // [B, 64]
                 const int*   __restrict__ instruction_id, // [B]
                 const float* __restrict__ patterns,       // [V, T, 64]
                 float*       __restrict__ out)            // [B, T, 64]
{
    __shared__ alignas(128) float buf[CHUNK_T * AD_];      // 16 KB
    __shared__ alignas(8) unsigned long long mbar;

    const unsigned bid   = blockIdx.x;
    const unsigned b     = bid >> 2;
    const unsigned chunk = bid & 3u;
    const unsigned tid   = threadIdx.x;

    const uint32_t mbar_addr = (uint32_t)__cvta_generic_to_shared(&mbar);
    const uint32_t buf_addr  = (uint32_t)__cvta_generic_to_shared(buf);

    if (tid == 0) {
        asm volatile("mbarrier.init.shared.b64 [%0], 1;"
                     :: "r"(mbar_addr) : "memory");
        asm volatile("fence.proxy.async.shared::cta;" ::: "memory");
    }
    __syncthreads();

    if (tid == 0) {
        const int iid = __ldg(&instruction_id[b]);
        const float* src = patterns + ((size_t)iid * T_ + (size_t)chunk * CHUNK_T) * AD_;
        asm volatile("mbarrier.arrive.expect_tx.shared.b64 _, [%0], %1;"
                     :: "r"(mbar_addr), "r"((unsigned)CHUNK_BYTES) : "memory");
        asm volatile("cp.async.bulk.shared::cta.global.mbarrier::complete_tx::bytes "
                     "[%0], [%1], %2, [%3];"
                     :: "r"(buf_addr), "l"(src), "r"((unsigned)CHUNK_BYTES), "r"(mbar_addr)
                     : "memory");
    }

    // Overlap with the bulk copy: per-thread invariant loads.
    const unsigned a4   = tid & 15u;     // float4 slot within 64-float action row
    const unsigned trow = tid >> 4;      // 0..15
    const float4 s = __ldg((const float4*)(start_state + (size_t)b * AD_) + a4);

    // Wait for the bulk copy (acquire orders subsequent smem reads).
    {
        uint32_t done;
        asm volatile(
            "{\n\t"
            ".reg .pred p;\n\t"
            "mbarrier.try_wait.parity.acquire.cta.shared::cta.b64 p, [%1], %2;\n\t"
            "selp.b32 %0, 1, 0, p;\n\t"
            "}"
            : "=r"(done) : "r"(mbar_addr), "r"(0u) : "memory");
        if (!done) {
            asm volatile(
                "{\n\t"
                ".reg .pred P1;\n\t"
                "WAIT_LOOP_%=:\n\t"
                "mbarrier.try_wait.parity.acquire.cta.shared::cta.b64 P1, [%0], %1, 0x989680;\n\t"
                "@P1 bra.uni WAIT_DONE_%=;\n\t"
                "bra.uni WAIT_LOOP_%=;\n\t"
                "WAIT_DONE_%=:\n\t"
                "}"
                :: "r"(mbar_addr), "r"(0u) : "memory");
        }
    }

    float4* __restrict__ dst =
        (float4*)(out + ((size_t)b * T_ + (size_t)chunk * CHUNK_T) * AD_);
    const float4* __restrict__ sb = (const float4*)buf;

#pragma unroll
    for (int i = 0; i < 4; i++) {
        const unsigned tl = trow + (unsigned)i * 16u;              // local t in chunk
        const float prog = (float)(chunk * CHUNK_T + tl) * (1.0f / (float)(T_ - 1));
        const float4 p = sb[tl * 16u + a4];
        float4 r;
        r.x = fmaf(prog, p.x, s.x);
        r.y = fmaf(prog, p.y, s.y);
        r.z = fmaf(prog, p.z, s.z);
        r.w = fmaf(prog, p.w, s.w);
        dst[tl * 16u + a4] = r;
    }
}

extern "C" void kernel_launch(void* const* d_in, const int* in_sizes, int n_in,
                              void* d_out, int out_size)
{
    const float* start_state    = (const float*)d_in[0];
    const int*   instruction_id = (const int*)  d_in[1];
    const float* patterns       = (const float*)d_in[27];
    float*       out            = (float*)d_out;

    traj_kernel<<<B_ * 4, TPB>>>(start_state, instruction_id, patterns, out);
}

// round 5
// speedup vs baseline: 1.0295x; 1.0295x over previous
#include <cuda_runtime.h>
#include <cstdint>

// out[b,t,a] = start_state[b,a] + (t/255) * patterns[iid[b], t, a]
// B=256, T=256, AD=64.
//
// R5: one CTA per batch row. 4 chunks x 16KB of patterns fetched with FOUR
// back-to-back cp.async.bulk ops issued up-front (64KB in flight per CTA,
// ~2 CTAs/SM -> ~19MB outstanding chip-wide), consumed through a 4-deep
// mbarrier pipeline. Bulk-engine queue depth replaces the per-warp MSHR cap.

#define B_   256
#define T_   256
#define AD_  64
#define TPB  512
#define NCHUNK 4
#define CHUNK_T 64
#define CHUNK_F4 (CHUNK_T * 16)            // 1024 float4 per chunk
#define CHUNK_BYTES (CHUNK_T * AD_ * 4)    // 16384

__global__ __launch_bounds__(TPB)
void traj_kernel(const float* __restrict__ start_state,    // [B, 64]
                 const int*   __restrict__ instruction_id, // [B]
                 const float* __restrict__ patterns,       // [V, T, 64]
                 float*       __restrict__ out)            // [B, T, 64]
{
    __shared__ alignas(128) float buf[NCHUNK][CHUNK_T * AD_];   // 64 KB
    __shared__ alignas(8) unsigned long long mbar[NCHUNK];

    const unsigned b   = blockIdx.x;
    const unsigned tid = threadIdx.x;

    const uint32_t mbar0 = (uint32_t)__cvta_generic_to_shared(&mbar[0]);

    if (tid == 0) {
#pragma unroll
        for (int c = 0; c < NCHUNK; c++)
            asm volatile("mbarrier.init.shared.b64 [%0], 1;"
                         :: "r"(mbar0 + c * 8) : "memory");
        asm volatile("fence.proxy.async.shared::cta;" ::: "memory");
    }
    __syncthreads();

    if (tid == 0) {
        const int iid = __ldg(&instruction_id[b]);
        const float* src0 = patterns + (size_t)iid * T_ * AD_;
#pragma unroll
        for (int c = 0; c < NCHUNK; c++) {
            const uint32_t mb = mbar0 + c * 8;
            const uint32_t dst_s = (uint32_t)__cvta_generic_to_shared(buf[c]);
            asm volatile("mbarrier.arrive.expect_tx.shared.b64 _, [%0], %1;"
                         :: "r"(mb), "r"((unsigned)CHUNK_BYTES) : "memory");
            asm volatile("cp.async.bulk.shared::cta.global.mbarrier::complete_tx::bytes "
                         "[%0], [%1], %2, [%3];"
                         :: "r"(dst_s), "l"(src0 + (size_t)c * CHUNK_T * AD_),
                            "r"((unsigned)CHUNK_BYTES), "r"(mb)
                         : "memory");
        }
    }

    // Overlapped with the bulk copies: invariant per-thread state.
    // Thread handles f4 indices j = tid and tid+512 within each chunk.
    // a4 = j & 15 is identical for both -> load start_state once.
    const unsigned a4 = tid & 15u;
    const float4 s = __ldg((const float4*)(start_state + (size_t)b * AD_) + a4);

    float4* __restrict__ dstb = (float4*)(out + (size_t)b * T_ * AD_);

#pragma unroll
    for (int c = 0; c < NCHUNK; c++) {
        // Wait for chunk c (acquire orders smem reads).
        const uint32_t mb = mbar0 + c * 8;
        {
            uint32_t done;
            asm volatile(
                "{\n\t"
                ".reg .pred p;\n\t"
                "mbarrier.try_wait.parity.acquire.cta.shared::cta.b64 p, [%1], %2;\n\t"
                "selp.b32 %0, 1, 0, p;\n\t"
                "}"
                : "=r"(done) : "r"(mb), "r"(0u) : "memory");
            if (!done) {
                asm volatile(
                    "{\n\t"
                    ".reg .pred P1;\n\t"
                    "WAIT_LOOP_%=:\n\t"
                    "mbarrier.try_wait.parity.acquire.cta.shared::cta.b64 P1, [%0], %1, 0x989680;\n\t"
                    "@P1 bra.uni WAIT_DONE_%=;\n\t"
                    "bra.uni WAIT_LOOP_%=;\n\t"
                    "WAIT_DONE_%=:\n\t"
                    "}"
                    :: "r"(mb), "r"(0u) : "memory");
            }
        }

        const float4* __restrict__ sb = (const float4*)buf[c];
#pragma unroll
        for (int k = 0; k < 2; k++) {
            const unsigned j  = tid + (unsigned)k * TPB;   // 0..1023
            const unsigned tl = j >> 4;                    // local t 0..63
            const float prog = (float)(c * CHUNK_T + tl) * (1.0f / (float)(T_ - 1));
            const float4 p = sb[j];
            float4 r;
            r.x = fmaf(prog, p.x, s.x);
            r.y = fmaf(prog, p.y, s.y);
            r.z = fmaf(prog, p.z, s.z);
            r.w = fmaf(prog, p.w, s.w);
            dstb[(size_t)c * CHUNK_F4 + j] = r;
        }
    }
}

extern "C" void kernel_launch(void* const* d_in, const int* in_sizes, int n_in,
                              void* d_out, int out_size)
{
    const float* start_state    = (const float*)d_in[0];
    const int*   instruction_id = (const int*)  d_in[1];
    const float* patterns       = (const float*)d_in[27];
    float*       out            = (float*)d_out;

    traj_kernel<<<B_, TPB>>>(start_state, instruction_id, patterns, out);
}